// round 11
// baseline (speedup 1.0000x reference)
#include <cuda_runtime.h>
#include <cuda_bf16.h>
#include <math.h>

// B=16, N=300, U=100, V=200, E=128, H=8, hd=16, L=3
// out: [16, 20000, 128] f32 (163.8 MB)

// Scratch (allocation-free: device globals)
__device__ float g_hE[16 * 38400];
__device__ float g_pu[16 * 100 * 128];
__device__ float g_pv[16 * 200 * 128];

// ---------------------------------------------------------------------------
// adj dtype detection, inlined per consumer CTA. 2048-word window.
// ---------------------------------------------------------------------------
template <int NT>
__device__ __forceinline__ int detect_adj_mode(const void* adjraw, int* s_flags)
{
    const unsigned int* aw = (const unsigned int*)adjraw;
    int tid = threadIdx.x;
    if (tid == 0) { s_flags[0] = 0; s_flags[1] = 0; }
    __syncthreads();
    int f32 = 0, multi = 0;
    #pragma unroll
    for (int i = tid; i < 2048; i += NT) {
        unsigned int v = aw[i];
        f32   |= (v == 0x3F800000u);
        multi |= (v != 0u && v != 1u && v != 0x3F800000u);
    }
    if (__any_sync(0xffffffffu, f32)   && (tid & 31) == 0) atomicOr(&s_flags[0], 1);
    if (__any_sync(0xffffffffu, multi) && (tid & 31) == 0) atomicOr(&s_flags[1], 1);
    __syncthreads();
    return s_flags[0] ? 2 : (s_flags[1] ? 1 : 0);   // 2=f32, 1=u8, 0=i32
}

// ---------------------------------------------------------------------------
// Fused 3-layer GAT: one CTA per (b, head). 1024 threads (32 warps).
// 4-row attention groups, j-split lanes (acc in float2 -> 64-reg budget),
// transposed att staging abT[i][4] and transposed adj for U-mode masks.
// smem floats:
//   [0,4800)      sWh   [300][16]
//   [4800,9600)   shh   persistent h [300][16]
//   [9600,9856)   sWt   16x16 transposed
//   [9856,9872)   sa1   [9872,9888) sa2
//   [9888,10188)  se1[300]   [10188,10488) se2[300]
//   [10488,15488) sadj  (20000 B, canonical u8, [u][v])
//   [15488,20488) sadjT (20000 B, [v][u])
//   [20488,46088) abT   [32 warps][200][4]
// total 184352 bytes -> 1 CTA/SM, 32 warps
// ---------------------------------------------------------------------------
#define GAT_THREADS 1024

__global__ void __launch_bounds__(GAT_THREADS, 1) gat_fused_kernel(
    const float* __restrict__ hin,
    const void*  __restrict__ adjraw,
    const float* __restrict__ Wl,   // [3][8][16][16]
    const float* __restrict__ al,   // [3][8][32]
    float* __restrict__ hout)
{
    extern __shared__ float sm[];
    float* sWh = sm;
    float* shh = sm + 4800;
    float* sWt = sm + 9600;
    float* sa1 = sm + 9856;
    float* sa2 = sm + 9872;
    float* se1 = sm + 9888;
    float* se2 = sm + 10188;
    unsigned char* sadj  = (unsigned char*)(sm + 10488);
    unsigned char* sadjT = (unsigned char*)(sm + 15488);
    float* sattb = sm + 20488;
    __shared__ int s_flags[2];

    const int tid  = threadIdx.x;
    const int lane = tid & 31;
    const int w    = tid >> 5;
    const int b    = blockIdx.x >> 3;
    const int hh   = blockIdx.x & 7;

    const float* hsrc = hin + (b * 8 + hh) * 4800;
    float* hdst = hout + (b * 8 + hh) * 4800;

    const int mode = detect_adj_mode<GAT_THREADS>(adjraw, s_flags);

    // ---- one-time loads ----
    for (int i = tid; i < 1200; i += GAT_THREADS)
        ((float4*)shh)[i] = ((const float4*)hsrc)[i];

    if (mode == 1) {
        const uint4* src = (const uint4*)((const unsigned char*)adjraw + b * 20000);
        for (int i = tid; i < 1250; i += GAT_THREADS)
            ((uint4*)sadj)[i] = src[i];
    } else if (mode == 0) {
        const int4* src = (const int4*)((const int*)adjraw + b * 20000);
        for (int i = tid; i < 5000; i += GAT_THREADS) {
            int4 v = src[i];
            ((uchar4*)sadj)[i] = make_uchar4(v.x != 0, v.y != 0, v.z != 0, v.w != 0);
        }
    } else {
        const float4* src = (const float4*)((const float*)adjraw + b * 20000);
        for (int i = tid; i < 5000; i += GAT_THREADS) {
            float4 v = src[i];
            ((uchar4*)sadj)[i] = make_uchar4(v.x != 0.f, v.y != 0.f, v.z != 0.f, v.w != 0.f);
        }
    }
    __syncthreads();
    // transpose adj: sadjT[v*100+u] = sadj[u*200+v]
    for (int j = tid; j < 20000; j += GAT_THREADS) {
        int v = j / 100, u = j - v * 100;
        sadjT[j] = sadj[u * 200 + v];
    }

    for (int l = 0; l < 3; l++) {
        const float* W = Wl + (l * 8 + hh) * 256;
        const float* a = al + (l * 8 + hh) * 32;
        if (tid < 256) {
            int j = tid >> 4, k = tid & 15;
            sWt[k * 16 + j] = W[tid];      // sWt[k][j] = W[j][k]
        }
        if (tid < 16) { sa1[tid] = a[tid]; sa2[tid] = a[16 + tid]; }
        __syncthreads();

        // ---- Wh = h @ W^T, e1 = Wh.a1, e2 = Wh.a2 ----
        for (int base = tid; base < 4800; base += GAT_THREADS) {
            int n = base >> 4, jj = base & 15;
            const float* hr = shh + n * 16;
            float s = 0.f;
            #pragma unroll
            for (int k = 0; k < 16; k++) s = fmaf(hr[k], sWt[k * 16 + jj], s);
            sWh[base] = s;
            float p1 = s * sa1[jj];
            float p2 = s * sa2[jj];
            #pragma unroll
            for (int off = 8; off; off >>= 1) {
                p1 += __shfl_xor_sync(0xffffffffu, p1, off);
                p2 += __shfl_xor_sync(0xffffffffu, p2, off);
            }
            if (jj == 0) { se1[n] = p1; se2[n] = p2; }
        }
        __syncthreads();

        // ---- attention: 75 groups of 4 rows (U:0..24 cost 2, V:25..74 cost 1)
        //      LPT: w<25 -> {U_w, V-group 25+w}; w>=25 -> g = 50+(w-25)+7k ----
        for (int k = 0; k < 4; k++) {
            int g;
            if (w < 25) {
                if (k == 0) g = w;               // U_w
                else if (k == 1) g = 25 + w;     // V-groups 25..49
                else break;
            } else {
                g = 50 + (w - 25) + 7 * k;       // V-groups 50..74
                if (g >= 75) break;
            }

            const bool modeU = (g < 25);
            const int  r0    = modeU ? (g << 2) : ((g - 25) << 2);

            float* ab = sattb + w * 800;         // [200][4]
            float rowc[4], selfe[4];
            float ssum[4] = {0.f, 0.f, 0.f, 0.f};

            if (modeU) {
                #pragma unroll
                for (int r = 0; r < 4; r++) {
                    rowc[r]  = se1[r0 + r];
                    float t  = rowc[r] + se2[r0 + r];
                    selfe[r] = (t > 0.f) ? t : 0.01f * t;
                }
                const float* cb = se2 + 100;
                #pragma unroll
                for (int kk = 0; kk < 6; kk++) {
                    int idx = lane + (kk << 5);
                    float cv = cb[idx];
                    unsigned int a4 = *(const unsigned int*)(sadjT + idx * 100 + r0);
                    float4 st;
                    float ev;
                    #define SCORE1(r, comp) { \
                        float t = rowc[r] + cv; \
                        t = (t > 0.f) ? t : 0.01f * t; \
                        ev = ((a4 >> (r * 8)) & 255u) ? 0.f : __expf(t - selfe[r]); \
                        st.comp = ev; ssum[r] += ev; }
                    SCORE1(0, x) SCORE1(1, y) SCORE1(2, z) SCORE1(3, w)
                    *(float4*)&ab[idx * 4] = st;
                }
                if (lane < 8) {
                    int idx = 192 + lane;
                    float cv = cb[idx];
                    unsigned int a4 = *(const unsigned int*)(sadjT + idx * 100 + r0);
                    float4 st;
                    float ev;
                    SCORE1(0, x) SCORE1(1, y) SCORE1(2, z) SCORE1(3, w)
                    *(float4*)&ab[idx * 4] = st;
                }
            } else {
                #pragma unroll
                for (int r = 0; r < 4; r++) {
                    int node = 100 + r0 + r;
                    rowc[r]  = se2[node];
                    float t  = se1[node] + rowc[r];
                    selfe[r] = (t > 0.f) ? t : 0.01f * t;
                }
                #pragma unroll
                for (int kk = 0; kk < 3; kk++) {
                    int idx = lane + (kk << 5);
                    float cv = se1[idx];
                    unsigned int a4 = *(const unsigned int*)(sadj + idx * 200 + r0);
                    float4 st;
                    float ev;
                    SCORE1(0, x) SCORE1(1, y) SCORE1(2, z) SCORE1(3, w)
                    *(float4*)&ab[idx * 4] = st;
                }
                if (lane < 4) {
                    int idx = 96 + lane;
                    float cv = se1[idx];
                    unsigned int a4 = *(const unsigned int*)(sadj + idx * 200 + r0);
                    float4 st;
                    float ev;
                    SCORE1(0, x) SCORE1(1, y) SCORE1(2, z) SCORE1(3, w)
                    *(float4*)&ab[idx * 4] = st;
                    #undef SCORE1
                }
            }
            __syncwarp();

            // ssum tree
            #pragma unroll
            for (int off = 16; off; off >>= 1) {
                #pragma unroll
                for (int r = 0; r < 4; r++)
                    ssum[r] += __shfl_xor_sync(0xffffffffu, ssum[r], off);
            }
            float inv[4];
            #pragma unroll
            for (int r = 0; r < 4; r++)
                inv[r] = 1.f / (ssum[r] + 1.f);    // self term exp(0)=1

            // ---- aggregation: lane=(v4=lane>>3, jh=lane&7), acc[r] float2 ----
            const int jh2 = (lane & 7) << 1, v4 = lane >> 3;
            const int accBase = modeU ? 100 : 0;
            float2 acc[4];
            #pragma unroll
            for (int r = 0; r < 4; r++) acc[r] = make_float2(0.f, 0.f);

            const float* whb = sWh + accBase * 16 + jh2;
            const int iters = modeU ? 50 : 25;
            #pragma unroll 5
            for (int ii = 0; ii < iters; ii++) {
                int i = v4 + (ii << 2);
                float2 wh2 = *(const float2*)&whb[i * 16];
                float4 a4  = *(const float4*)&ab[i * 4];
                acc[0].x = fmaf(a4.x, wh2.x, acc[0].x);
                acc[0].y = fmaf(a4.x, wh2.y, acc[0].y);
                acc[1].x = fmaf(a4.y, wh2.x, acc[1].x);
                acc[1].y = fmaf(a4.y, wh2.y, acc[1].y);
                acc[2].x = fmaf(a4.z, wh2.x, acc[2].x);
                acc[2].y = fmaf(a4.z, wh2.y, acc[2].y);
                acc[3].x = fmaf(a4.w, wh2.x, acc[3].x);
                acc[3].y = fmaf(a4.w, wh2.y, acc[3].y);
            }
            // reduce across v4 (offsets 8, 16)
            #pragma unroll
            for (int off = 8; off <= 16; off <<= 1) {
                #pragma unroll
                for (int r = 0; r < 4; r++) {
                    acc[r].x += __shfl_xor_sync(0xffffffffu, acc[r].x, off);
                    acc[r].y += __shfl_xor_sync(0xffffffffu, acc[r].y, off);
                }
            }
            if (v4 == 0) {                       // lanes 0..7 hold jh = lane
                #pragma unroll
                for (int r = 0; r < 4; r++) {
                    int node = modeU ? (r0 + r) : (100 + r0 + r);
                    float2 ws = *(const float2*)&sWh[node * 16 + jh2];
                    float2 res;
                    res.x = (acc[r].x + ws.x) * inv[r];
                    res.y = (acc[r].y + ws.y) * inv[r];
                    res.x = (res.x > 0.f) ? res.x : expm1f(res.x);
                    res.y = (res.y > 0.f) ? res.y : expm1f(res.y);
                    if (l == 2)
                        *(float2*)&hdst[node * 16 + jh2] = res;
                    else
                        *(float2*)&shh[node * 16 + jh2] = res;
                }
            }
            __syncwarp();
        }
        __syncthreads();   // shh fully written before next layer's Wh phase
    }
}

// ---------------------------------------------------------------------------
// pu = hE[:, :U] @ W1^T ; pv = hE[:, U:] @ W2^T
// ---------------------------------------------------------------------------
__global__ void __launch_bounds__(256, 1) pupv_kernel(
    const float* __restrict__ hE,
    const float* __restrict__ Wlast,  // [128][257]
    float* __restrict__ pu, float* __restrict__ pv)
{
    extern __shared__ float sm[];
    float* hsm = sm;           // 20*132
    float* Wsm = sm + 2640;    // 128*132

    const int blk = blockIdx.x;
    const int b = blk / 15, t = blk % 15;
    const bool isU = (t < 5);
    const int n0 = isU ? t * 20 : 100 + (t - 5) * 20;
    const int coff = isU ? 0 : 128;
    const int tid = threadIdx.x;

    for (int i = tid; i < 128 * 128; i += 256) {
        int e = i >> 7, k = i & 127;
        Wsm[e * 132 + k] = Wlast[e * 257 + coff + k];
    }
    for (int i = tid; i < 20 * 128; i += 256) {
        int n = i >> 7, k = i & 127;
        hsm[n * 132 + k] = hE[b * 38400 + (n0 + n) * 128 + k];
    }
    __syncthreads();

    const int e = tid & 127, half = tid >> 7;
    float acc[10];
    #pragma unroll
    for (int n = 0; n < 10; n++) acc[n] = 0.f;
    const float* wrow  = Wsm + e * 132;
    const float* hbase = hsm + (half * 10) * 132;

    #pragma unroll 8
    for (int k4 = 0; k4 < 32; k4++) {
        float4 wv = *(const float4*)&wrow[k4 * 4];
        #pragma unroll
        for (int n = 0; n < 10; n++) {
            float4 hv = *(const float4*)&hbase[n * 132 + k4 * 4];
            acc[n] = fmaf(wv.x, hv.x, acc[n]);
            acc[n] = fmaf(wv.y, hv.y, acc[n]);
            acc[n] = fmaf(wv.z, hv.z, acc[n]);
            acc[n] = fmaf(wv.w, hv.w, acc[n]);
        }
    }
    int nodeBase = isU ? (b * 100 + n0 + half * 10) : (b * 200 + (n0 - 100) + half * 10);
    float* dst = isU ? (pu + (size_t)nodeBase * 128) : (pv + (size_t)nodeBase * 128);
    #pragma unroll
    for (int n = 0; n < 10; n++) dst[n * 128 + e] = acc[n];
}

// ---------------------------------------------------------------------------
// out[b,u,v,:] = mask*(pu[b,u,:] + pv[b,v,:]) + weights[b,u,v]*wl
// grid: 16 b * 9 balanced u-slices = 144 CTAs, 512 threads, streaming stores
// ---------------------------------------------------------------------------
__global__ void __launch_bounds__(512, 1) out_kernel(
    const float* __restrict__ pu, const float* __restrict__ pv,
    const void* __restrict__ adjraw, const float* __restrict__ weights,
    const float* __restrict__ Wlast, float* __restrict__ out)
{
    extern __shared__ float sm[];
    float* spv = sm;            // 200*128
    float* spu = sm + 25600;    // up to 12*128
    float* swl = sm + 27136;    // 128
    __shared__ int s_flags[2];

    const int b = blockIdx.x / 9, gslice = blockIdx.x % 9;
    const int u0 = (gslice * 100) / 9;
    const int u1 = ((gslice + 1) * 100) / 9;
    const int nu = u1 - u0;
    const int tid = threadIdx.x, lane = tid & 31, w = tid >> 5;

    const int mode = detect_adj_mode<512>(adjraw, s_flags);

    for (int i = tid; i < 6400; i += 512)
        ((float4*)spv)[i] = ((const float4*)(pv + b * 25600))[i];
    for (int i = tid; i < nu * 32; i += 512)
        ((float4*)spu)[i] = ((const float4*)(pu + (b * 100 + u0) * 128))[i];
    if (tid < 128) swl[tid] = Wlast[tid * 257 + 256];
    __syncthreads();

    const float4 wl4 = *(const float4*)&swl[lane * 4];
    for (int iu = 0; iu < nu; iu++) {
        const int u = u0 + iu;
        const int abase = (b * 100 + u) * 200;
        const float* wrow = weights + abase;
        const float4 pu4 = *(const float4*)&spu[iu * 128 + lane * 4];
        float* obase = out + ((size_t)(b * 100 + u)) * 200 * 128;
        for (int v = w; v < 200; v += 16) {
            float msk;
            if (mode == 0)      msk = ((const int*)adjraw)[abase + v] ? 0.f : 1.f;
            else if (mode == 1) msk = ((const unsigned char*)adjraw)[abase + v] ? 0.f : 1.f;
            else                msk = (((const float*)adjraw)[abase + v] != 0.f) ? 0.f : 1.f;
            const float wt  = wrow[v];
            const float4 pv4 = *(const float4*)&spv[v * 128 + lane * 4];
            float4 o;
            o.x = msk * (pu4.x + pv4.x) + wt * wl4.x;
            o.y = msk * (pu4.y + pv4.y) + wt * wl4.y;
            o.z = msk * (pu4.z + pv4.z) + wt * wl4.z;
            o.w = msk * (pu4.w + pv4.w) + wt * wl4.w;
            __stcs((float4*)&obase[(size_t)v * 128 + lane * 4], o);
        }
    }
}

// ---------------------------------------------------------------------------
extern "C" void kernel_launch(void* const* d_in, const int* in_sizes, int n_in,
                              void* d_out, int out_size)
{
    (void)in_sizes; (void)n_in; (void)out_size;
    const float* x              = (const float*)d_in[0];
    const void*  adj_raw        = (const void*)d_in[1];
    const float* weights        = (const float*)d_in[2];
    const float* Wlayers        = (const float*)d_in[3];
    const float* alayers        = (const float*)d_in[4];
    const float* Wlast          = (const float*)d_in[5];
    float* out = (float*)d_out;

    float *dH, *dpu, *dpv;
    cudaGetSymbolAddress((void**)&dH, g_hE);
    cudaGetSymbolAddress((void**)&dpu, g_pu);
    cudaGetSymbolAddress((void**)&dpv, g_pv);

    const int SM1 = 46088 * 4;                  // 184352
    const int SM2 = (2640 + 128 * 132) * 4;     // 78144
    const int SM3 = (27136 + 128) * 4;          // 109056
    cudaFuncSetAttribute(gat_fused_kernel, cudaFuncAttributeMaxDynamicSharedMemorySize, SM1);
    cudaFuncSetAttribute(pupv_kernel,      cudaFuncAttributeMaxDynamicSharedMemorySize, SM2);
    cudaFuncSetAttribute(out_kernel,       cudaFuncAttributeMaxDynamicSharedMemorySize, SM3);

    gat_fused_kernel<<<128, GAT_THREADS, SM1>>>(x, adj_raw, Wlayers, alayers, dH);
    pupv_kernel<<<240, 256, SM2>>>(dH, Wlast, dpu, dpv);
    out_kernel<<<144, 512, SM3>>>(dpu, dpv, adj_raw, weights, Wlast, out);
}

// round 12
// speedup vs baseline: 1.3825x; 1.3825x over previous
#include <cuda_runtime.h>
#include <cuda_bf16.h>
#include <math.h>

// B=16, N=300, U=100, V=200, E=128, H=8, hd=16, L=3
// out: [16, 20000, 128] f32 (163.8 MB)

// Scratch (allocation-free: device globals)
__device__ float g_hE[16 * 38400];
__device__ float g_pu[16 * 100 * 128];
__device__ float g_pv[16 * 200 * 128];

// ---------------------------------------------------------------------------
// adj dtype detection, inlined per consumer CTA. 2048-word window:
//   any word == 0x3F800000           -> float32
//   any word not in {0,1,0x3F800000} -> packed uint8 (p=0.3 -> certain)
//   else                             -> int32
// ---------------------------------------------------------------------------
template <int NT>
__device__ __forceinline__ int detect_adj_mode(const void* adjraw, int* s_flags)
{
    const unsigned int* aw = (const unsigned int*)adjraw;
    int tid = threadIdx.x;
    if (tid == 0) { s_flags[0] = 0; s_flags[1] = 0; }
    __syncthreads();
    int f32 = 0, multi = 0;
    #pragma unroll
    for (int i = tid; i < 2048; i += NT) {
        unsigned int v = aw[i];
        f32   |= (v == 0x3F800000u);
        multi |= (v != 0u && v != 1u && v != 0x3F800000u);
    }
    if (__any_sync(0xffffffffu, f32)   && (tid & 31) == 0) atomicOr(&s_flags[0], 1);
    if (__any_sync(0xffffffffu, multi) && (tid & 31) == 0) atomicOr(&s_flags[1], 1);
    __syncthreads();
    return s_flags[0] ? 2 : (s_flags[1] ? 1 : 0);   // 2=f32, 1=u8, 0=i32
}

// ---------------------------------------------------------------------------
// Fused 3-layer GAT: one CTA per (b, head). 768 threads (24 warps).
// (= round-8 proven structure; only the Wh inner product is re-vectorized:
//    W row-major padded to 20 floats -> 8x LDS.128 instead of 20 LDS.)
// smem floats:
//   [0,4800)      sWh   [300][16]
//   [4800,9600)   shh   persistent h [300][16]
//   [9600,9920)   sW    [16][20] row-major padded
//   [9920,9936)   sa1   [9936,9952) sa2
//   [9952,10252)  se1[300]   [10252,10552) se2[300]
//   [10552,15552) sadj (20000 B, canonical u8)
//   [15552,35136) sattb [24 warps][4][204]
// total 140544 bytes -> 1 CTA/SM, 24 warps
// ---------------------------------------------------------------------------
#define GAT_THREADS 768

__global__ void __launch_bounds__(GAT_THREADS, 1) gat_fused_kernel(
    const float* __restrict__ hin,
    const void*  __restrict__ adjraw,
    const float* __restrict__ Wl,   // [3][8][16][16]
    const float* __restrict__ al,   // [3][8][32]
    float* __restrict__ hout)
{
    extern __shared__ float sm[];
    float* sWh = sm;
    float* shh = sm + 4800;
    float* sW  = sm + 9600;
    float* sa1 = sm + 9920;
    float* sa2 = sm + 9936;
    float* se1 = sm + 9952;
    float* se2 = sm + 10252;
    unsigned char* sadj = (unsigned char*)(sm + 10552);
    float* sattb = sm + 15552;
    __shared__ int s_flags[2];

    const int tid  = threadIdx.x;
    const int lane = tid & 31;
    const int w    = tid >> 5;
    const int b    = blockIdx.x >> 3;
    const int hh   = blockIdx.x & 7;

    const float* hsrc = hin + (b * 8 + hh) * 4800;
    float* hdst = hout + (b * 8 + hh) * 4800;

    const int mode = detect_adj_mode<GAT_THREADS>(adjraw, s_flags);

    // ---- one-time loads ----
    for (int i = tid; i < 1200; i += GAT_THREADS)
        ((float4*)shh)[i] = ((const float4*)hsrc)[i];

    if (mode == 1) {
        const uint4* src = (const uint4*)((const unsigned char*)adjraw + b * 20000);
        for (int i = tid; i < 1250; i += GAT_THREADS)
            ((uint4*)sadj)[i] = src[i];
    } else if (mode == 0) {
        const int4* src = (const int4*)((const int*)adjraw + b * 20000);
        for (int i = tid; i < 5000; i += GAT_THREADS) {
            int4 v = src[i];
            ((uchar4*)sadj)[i] = make_uchar4(v.x != 0, v.y != 0, v.z != 0, v.w != 0);
        }
    } else {
        const float4* src = (const float4*)((const float*)adjraw + b * 20000);
        for (int i = tid; i < 5000; i += GAT_THREADS) {
            float4 v = src[i];
            ((uchar4*)sadj)[i] = make_uchar4(v.x != 0.f, v.y != 0.f, v.z != 0.f, v.w != 0.f);
        }
    }

    for (int l = 0; l < 3; l++) {
        const float* W = Wl + (l * 8 + hh) * 256;
        const float* a = al + (l * 8 + hh) * 32;
        if (tid < 256) {
            int j = tid >> 4, k = tid & 15;
            sW[j * 20 + k] = W[tid];       // row-major, padded row of 20
        }
        if (tid < 16) { sa1[tid] = a[tid]; sa2[tid] = a[16 + tid]; }
        __syncthreads();

        // ---- Wh = h @ W^T (vectorized dot), e1 = Wh.a1, e2 = Wh.a2 ----
        for (int base = tid; base < 4800; base += GAT_THREADS) {
            int n = base >> 4, jj = base & 15;
            const float4* hr4 = (const float4*)(shh + n * 16);
            const float4* wr4 = (const float4*)(sW + jj * 20);   // 80B-aligned
            float4 h0 = hr4[0], h1 = hr4[1], h2 = hr4[2], h3 = hr4[3];
            float4 w0 = wr4[0], w1 = wr4[1], w2 = wr4[2], w3 = wr4[3];
            float s = 0.f;
            s = fmaf(h0.x, w0.x, s); s = fmaf(h0.y, w0.y, s);
            s = fmaf(h0.z, w0.z, s); s = fmaf(h0.w, w0.w, s);
            s = fmaf(h1.x, w1.x, s); s = fmaf(h1.y, w1.y, s);
            s = fmaf(h1.z, w1.z, s); s = fmaf(h1.w, w1.w, s);
            s = fmaf(h2.x, w2.x, s); s = fmaf(h2.y, w2.y, s);
            s = fmaf(h2.z, w2.z, s); s = fmaf(h2.w, w2.w, s);
            s = fmaf(h3.x, w3.x, s); s = fmaf(h3.y, w3.y, s);
            s = fmaf(h3.z, w3.z, s); s = fmaf(h3.w, w3.w, s);
            sWh[base] = s;
            float p1 = s * sa1[jj];
            float p2 = s * sa2[jj];
            #pragma unroll
            for (int off = 8; off; off >>= 1) {
                p1 += __shfl_xor_sync(0xffffffffu, p1, off);
                p2 += __shfl_xor_sync(0xffffffffu, p2, off);
            }
            if (jj == 0) { se1[n] = p1; se2[n] = p2; }
        }
        __syncthreads();

        // ---- attention: 75 groups of 4 rows, LPT schedule (r8-proven) ----
        for (int k = 0; k < 4; k++) {
            int g;
            if (k == 0)      g = w;                                   // U0..U23
            else if (k == 1) g = (w == 3) ? 24
                               : (25 + w - (w > 3 ? 1 : 0));          // U24 / V25..47
            else if (k == 2) g = 48 + w;                              // V48..71
            else { if (w >= 3) break; g = 72 + w; }                   // V72..74

            const bool modeU = (g < 25);
            const int  r0    = modeU ? (g << 2) : ((g - 25) << 2);

            float* ab = sattb + ((w << 2) * 204);
            float rowc[4], selfe[4];
            float ssum[4] = {0.f, 0.f, 0.f, 0.f};

            if (modeU) {
                #pragma unroll
                for (int r = 0; r < 4; r++) {
                    rowc[r]  = se1[r0 + r];
                    float t  = rowc[r] + se2[r0 + r];
                    selfe[r] = (t > 0.f) ? t : 0.01f * t;
                }
                const float* cb = se2 + 100;
                const unsigned char* adjU = sadj + r0 * 200;
                #pragma unroll
                for (int kk = 0; kk < 6; kk++) {
                    int idx = lane + (kk << 5);
                    float cv = cb[idx];
                    #pragma unroll
                    for (int r = 0; r < 4; r++) {
                        float t = rowc[r] + cv;
                        t = (t > 0.f) ? t : 0.01f * t;
                        float ev = __expf(t - selfe[r]);
                        ev = adjU[r * 200 + idx] ? 0.f : ev;
                        ab[r * 204 + idx] = ev;
                        ssum[r] += ev;
                    }
                }
                if (lane < 8) {                    // tail: idx = 192+lane
                    int idx = 192 + lane;
                    float cv = cb[idx];
                    #pragma unroll
                    for (int r = 0; r < 4; r++) {
                        float t = rowc[r] + cv;
                        t = (t > 0.f) ? t : 0.01f * t;
                        float ev = __expf(t - selfe[r]);
                        ev = adjU[r * 200 + idx] ? 0.f : ev;
                        ab[r * 204 + idx] = ev;
                        ssum[r] += ev;
                    }
                }
            } else {
                #pragma unroll
                for (int r = 0; r < 4; r++) {
                    int node = 100 + r0 + r;
                    rowc[r]  = se2[node];
                    float t  = se1[node] + rowc[r];
                    selfe[r] = (t > 0.f) ? t : 0.01f * t;
                }
                const unsigned char* adjC = sadj + r0;
                #pragma unroll
                for (int kk = 0; kk < 3; kk++) {
                    int idx = lane + (kk << 5);
                    float cv = se1[idx];
                    unsigned int aw4 = *(const unsigned int*)(adjC + idx * 200);
                    #pragma unroll
                    for (int r = 0; r < 4; r++) {
                        float t = rowc[r] + cv;
                        t = (t > 0.f) ? t : 0.01f * t;
                        float ev = __expf(t - selfe[r]);
                        ev = ((aw4 >> (r * 8)) & 255u) ? 0.f : ev;
                        ab[r * 204 + idx] = ev;
                        ssum[r] += ev;
                    }
                }
                if (lane < 4) {                    // tail: idx = 96+lane
                    int idx = 96 + lane;
                    float cv = se1[idx];
                    unsigned int aw4 = *(const unsigned int*)(adjC + idx * 200);
                    #pragma unroll
                    for (int r = 0; r < 4; r++) {
                        float t = rowc[r] + cv;
                        t = (t > 0.f) ? t : 0.01f * t;
                        float ev = __expf(t - selfe[r]);
                        ev = ((aw4 >> (r * 8)) & 255u) ? 0.f : ev;
                        ab[r * 204 + idx] = ev;
                        ssum[r] += ev;
                    }
                }
            }
            __syncwarp();

            // ssum tree (independent of aggregation below -> latency overlapped)
            #pragma unroll
            for (int off = 16; off; off >>= 1) {
                #pragma unroll
                for (int r = 0; r < 4; r++)
                    ssum[r] += __shfl_xor_sync(0xffffffffu, ssum[r], off);
            }
            float inv[4];
            #pragma unroll
            for (int r = 0; r < 4; r++)
                inv[r] = 1.f / (ssum[r] + 1.f);    // self term exp(0)=1

            // ---- aggregation over raw ev; normalize at the end ----
            const int q4 = (lane & 3) << 2, v4 = lane >> 2;
            float4 acc[4];
            #pragma unroll
            for (int r = 0; r < 4; r++) acc[r] = make_float4(0.f, 0.f, 0.f, 0.f);

            if (modeU) {
                const float* whb = sWh + 100 * 16 + q4;
                #pragma unroll 5
                for (int ii = 0; ii < 25; ii++) {
                    int i = v4 + (ii << 3);
                    float4 w4 = *(const float4*)&whb[i * 16];
                    #pragma unroll
                    for (int r = 0; r < 4; r++) {
                        float av = ab[r * 204 + i];
                        acc[r].x = fmaf(av, w4.x, acc[r].x);
                        acc[r].y = fmaf(av, w4.y, acc[r].y);
                        acc[r].z = fmaf(av, w4.z, acc[r].z);
                        acc[r].w = fmaf(av, w4.w, acc[r].w);
                    }
                }
            } else {
                const float* whb = sWh + q4;
                #pragma unroll 4
                for (int ii = 0; ii < 13; ii++) {
                    int i = v4 + (ii << 3);
                    if (i < 100) {
                        float4 w4 = *(const float4*)&whb[i * 16];
                        #pragma unroll
                        for (int r = 0; r < 4; r++) {
                            float av = ab[r * 204 + i];
                            acc[r].x = fmaf(av, w4.x, acc[r].x);
                            acc[r].y = fmaf(av, w4.y, acc[r].y);
                            acc[r].z = fmaf(av, w4.z, acc[r].z);
                            acc[r].w = fmaf(av, w4.w, acc[r].w);
                        }
                    }
                }
            }
            #pragma unroll
            for (int off = 4; off < 32; off <<= 1) {
                #pragma unroll
                for (int r = 0; r < 4; r++) {
                    acc[r].x += __shfl_xor_sync(0xffffffffu, acc[r].x, off);
                    acc[r].y += __shfl_xor_sync(0xffffffffu, acc[r].y, off);
                    acc[r].z += __shfl_xor_sync(0xffffffffu, acc[r].z, off);
                    acc[r].w += __shfl_xor_sync(0xffffffffu, acc[r].w, off);
                }
            }
            if (v4 == 0) {
                #pragma unroll
                for (int r = 0; r < 4; r++) {
                    int node = modeU ? (r0 + r) : (100 + r0 + r);
                    float4 ws = *(const float4*)&sWh[node * 16 + q4];
                    float4 res;
                    res.x = (acc[r].x + ws.x) * inv[r];
                    res.y = (acc[r].y + ws.y) * inv[r];
                    res.z = (acc[r].z + ws.z) * inv[r];
                    res.w = (acc[r].w + ws.w) * inv[r];
                    res.x = (res.x > 0.f) ? res.x : expm1f(res.x);
                    res.y = (res.y > 0.f) ? res.y : expm1f(res.y);
                    res.z = (res.z > 0.f) ? res.z : expm1f(res.z);
                    res.w = (res.w > 0.f) ? res.w : expm1f(res.w);
                    if (l == 2)
                        *(float4*)&hdst[node * 16 + q4] = res;
                    else
                        *(float4*)&shh[node * 16 + q4] = res;
                }
            }
            __syncwarp();
        }
        __syncthreads();   // shh fully written before next layer's Wh phase
    }
}

// ---------------------------------------------------------------------------
// pu = hE[:, :U] @ W1^T ; pv = hE[:, U:] @ W2^T
// Each thread: 2 e-columns (eq, eq+64) x 5 nodes -> 7 LDS.128 per 40 FMA.
// grid: 16 b * 15 tiles of 20 nodes
// ---------------------------------------------------------------------------
__global__ void __launch_bounds__(256, 1) pupv_kernel(
    const float* __restrict__ hE,
    const float* __restrict__ Wlast,  // [128][257]
    float* __restrict__ pu, float* __restrict__ pv)
{
    extern __shared__ float sm[];
    float* hsm = sm;           // 20*132
    float* Wsm = sm + 2640;    // 128*132

    const int blk = blockIdx.x;
    const int b = blk / 15, t = blk % 15;
    const bool isU = (t < 5);
    const int n0 = isU ? t * 20 : 100 + (t - 5) * 20;
    const int coff = isU ? 0 : 128;
    const int tid = threadIdx.x;

    for (int i = tid; i < 128 * 128; i += 256) {
        int e = i >> 7, k = i & 127;
        Wsm[e * 132 + k] = Wlast[e * 257 + coff + k];
    }
    for (int i = tid; i < 20 * 128; i += 256) {
        int n = i >> 7, k = i & 127;
        hsm[n * 132 + k] = hE[b * 38400 + (n0 + n) * 128 + k];
    }
    __syncthreads();

    const int eq = tid & 63, half = tid >> 6;   // 4 n-groups of 5
    float acc0[5], acc1[5];
    #pragma unroll
    for (int n = 0; n < 5; n++) { acc0[n] = 0.f; acc1[n] = 0.f; }
    const float* wrow0 = Wsm + eq * 132;
    const float* wrow1 = Wsm + (eq + 64) * 132;
    const float* hbase = hsm + (half * 5) * 132;

    #pragma unroll 8
    for (int k4 = 0; k4 < 32; k4++) {
        float4 w0 = *(const float4*)&wrow0[k4 * 4];
        float4 w1 = *(const float4*)&wrow1[k4 * 4];
        #pragma unroll
        for (int n = 0; n < 5; n++) {
            float4 hv = *(const float4*)&hbase[n * 132 + k4 * 4];
            acc0[n] = fmaf(w0.x, hv.x, acc0[n]);
            acc0[n] = fmaf(w0.y, hv.y, acc0[n]);
            acc0[n] = fmaf(w0.z, hv.z, acc0[n]);
            acc0[n] = fmaf(w0.w, hv.w, acc0[n]);
            acc1[n] = fmaf(w1.x, hv.x, acc1[n]);
            acc1[n] = fmaf(w1.y, hv.y, acc1[n]);
            acc1[n] = fmaf(w1.z, hv.z, acc1[n]);
            acc1[n] = fmaf(w1.w, hv.w, acc1[n]);
        }
    }
    int nodeBase = isU ? (b * 100 + n0 + half * 5) : (b * 200 + (n0 - 100) + half * 5);
    float* dst = isU ? (pu + (size_t)nodeBase * 128) : (pv + (size_t)nodeBase * 128);
    #pragma unroll
    for (int n = 0; n < 5; n++) {
        dst[n * 128 + eq]      = acc0[n];
        dst[n * 128 + eq + 64] = acc1[n];
    }
}

// ---------------------------------------------------------------------------
// out[b,u,v,:] = mask*(pu[b,u,:] + pv[b,v,:]) + weights[b,u,v]*wl
// grid: 16 b * 9 balanced u-slices = 144 CTAs, 512 threads, streaming stores
// ---------------------------------------------------------------------------
__global__ void __launch_bounds__(512, 1) out_kernel(
    const float* __restrict__ pu, const float* __restrict__ pv,
    const void* __restrict__ adjraw, const float* __restrict__ weights,
    const float* __restrict__ Wlast, float* __restrict__ out)
{
    extern __shared__ float sm[];
    float* spv = sm;            // 200*128
    float* spu = sm + 25600;    // up to 12*128
    float* swl = sm + 27136;    // 128
    __shared__ int s_flags[2];

    const int b = blockIdx.x / 9, gslice = blockIdx.x % 9;
    const int u0 = (gslice * 100) / 9;
    const int u1 = ((gslice + 1) * 100) / 9;
    const int nu = u1 - u0;
    const int tid = threadIdx.x, lane = tid & 31, w = tid >> 5;

    const int mode = detect_adj_mode<512>(adjraw, s_flags);

    for (int i = tid; i < 6400; i += 512)
        ((float4*)spv)[i] = ((const float4*)(pv + b * 25600))[i];
    for (int i = tid; i < nu * 32; i += 512)
        ((float4*)spu)[i] = ((const float4*)(pu + (b * 100 + u0) * 128))[i];
    if (tid < 128) swl[tid] = Wlast[tid * 257 + 256];
    __syncthreads();

    const float4 wl4 = *(const float4*)&swl[lane * 4];
    for (int iu = 0; iu < nu; iu++) {
        const int u = u0 + iu;
        const int abase = (b * 100 + u) * 200;
        const float* wrow = weights + abase;
        const float4 pu4 = *(const float4*)&spu[iu * 128 + lane * 4];
        float* obase = out + ((size_t)(b * 100 + u)) * 200 * 128;
        for (int v = w; v < 200; v += 16) {
            float msk;
            if (mode == 0)      msk = ((const int*)adjraw)[abase + v] ? 0.f : 1.f;
            else if (mode == 1) msk = ((const unsigned char*)adjraw)[abase + v] ? 0.f : 1.f;
            else                msk = (((const float*)adjraw)[abase + v] != 0.f) ? 0.f : 1.f;
            const float wt  = wrow[v];
            const float4 pv4 = *(const float4*)&spv[v * 128 + lane * 4];
            float4 o;
            o.x = msk * (pu4.x + pv4.x) + wt * wl4.x;
            o.y = msk * (pu4.y + pv4.y) + wt * wl4.y;
            o.z = msk * (pu4.z + pv4.z) + wt * wl4.z;
            o.w = msk * (pu4.w + pv4.w) + wt * wl4.w;
            __stcs((float4*)&obase[(size_t)v * 128 + lane * 4], o);
        }
    }
}

// ---------------------------------------------------------------------------
extern "C" void kernel_launch(void* const* d_in, const int* in_sizes, int n_in,
                              void* d_out, int out_size)
{
    (void)in_sizes; (void)n_in; (void)out_size;
    const float* x              = (const float*)d_in[0];
    const void*  adj_raw        = (const void*)d_in[1];
    const float* weights        = (const float*)d_in[2];
    const float* Wlayers        = (const float*)d_in[3];
    const float* alayers        = (const float*)d_in[4];
    const float* Wlast          = (const float*)d_in[5];
    float* out = (float*)d_out;

    float *dH, *dpu, *dpv;
    cudaGetSymbolAddress((void**)&dH, g_hE);
    cudaGetSymbolAddress((void**)&dpu, g_pu);
    cudaGetSymbolAddress((void**)&dpv, g_pv);

    const int SM1 = 35136 * 4;                  // 140544
    const int SM2 = (2640 + 128 * 132) * 4;     // 78144
    const int SM3 = (27136 + 128) * 4;          // 109056
    cudaFuncSetAttribute(gat_fused_kernel, cudaFuncAttributeMaxDynamicSharedMemorySize, SM1);
    cudaFuncSetAttribute(pupv_kernel,      cudaFuncAttributeMaxDynamicSharedMemorySize, SM2);
    cudaFuncSetAttribute(out_kernel,       cudaFuncAttributeMaxDynamicSharedMemorySize, SM3);

    gat_fused_kernel<<<128, GAT_THREADS, SM1>>>(x, adj_raw, Wlayers, alayers, dH);
    pupv_kernel<<<240, 256, SM2>>>(dH, Wlast, dpu, dpv);
    out_kernel<<<144, 512, SM3>>>(dpu, dpv, adj_raw, weights, Wlast, out);
}

// round 13
// speedup vs baseline: 1.4211x; 1.0279x over previous
#include <cuda_runtime.h>
#include <cuda_bf16.h>
#include <math.h>

// B=16, N=300, U=100, V=200, E=128, H=8, hd=16, L=3
// out: [16, 20000, 128] f32 (163.8 MB)

// Scratch (allocation-free: device globals)
__device__ float g_hE[16 * 38400];
__device__ float g_pu[16 * 100 * 128];
__device__ float g_pv[16 * 200 * 128];

// ---------------------------------------------------------------------------
// adj dtype detection, inlined per consumer CTA. 2048-word window:
//   any word == 0x3F800000           -> float32
//   any word not in {0,1,0x3F800000} -> packed uint8 (p=0.3 -> certain)
//   else                             -> int32
// ---------------------------------------------------------------------------
template <int NT>
__device__ __forceinline__ int detect_adj_mode(const void* adjraw, int* s_flags)
{
    const unsigned int* aw = (const unsigned int*)adjraw;
    int tid = threadIdx.x;
    if (tid == 0) { s_flags[0] = 0; s_flags[1] = 0; }
    __syncthreads();
    int f32 = 0, multi = 0;
    #pragma unroll
    for (int i = tid; i < 2048; i += NT) {
        unsigned int v = aw[i];
        f32   |= (v == 0x3F800000u);
        multi |= (v != 0u && v != 1u && v != 0x3F800000u);
    }
    if (__any_sync(0xffffffffu, f32)   && (tid & 31) == 0) atomicOr(&s_flags[0], 1);
    if (__any_sync(0xffffffffu, multi) && (tid & 31) == 0) atomicOr(&s_flags[1], 1);
    __syncthreads();
    return s_flags[0] ? 2 : (s_flags[1] ? 1 : 0);   // 2=f32, 1=u8, 0=i32
}

// ---------------------------------------------------------------------------
// Fused 3-layer GAT: one CTA per (b, head). 768 threads (24 warps).
// = round-8 structure exactly, ONE change: attention staging transposed to
//   ab[idx][4] so score uses STS.128 and aggregation uses LDS.128.
// smem floats:
//   [0,4800)      sWh   [300][16]
//   [4800,9600)   shh   persistent h [300][16]
//   [9600,9856)   sWt   16x16 transposed (r8 layout)
//   [9856,9872)   sa1   [9872,9888) sa2
//   [9888,10188)  se1[300]   [10188,10488) se2[300]
//   [10488,15488) sadj (20000 B, canonical u8)
//   [15488,35072) sattb [24 warps][204][4]
// total 140288 bytes -> 1 CTA/SM, 24 warps
// ---------------------------------------------------------------------------
#define GAT_THREADS 768

__global__ void __launch_bounds__(GAT_THREADS, 1) gat_fused_kernel(
    const float* __restrict__ hin,
    const void*  __restrict__ adjraw,
    const float* __restrict__ Wl,   // [3][8][16][16]
    const float* __restrict__ al,   // [3][8][32]
    float* __restrict__ hout)
{
    extern __shared__ float sm[];
    float* sWh = sm;
    float* shh = sm + 4800;
    float* sWt = sm + 9600;
    float* sa1 = sm + 9856;
    float* sa2 = sm + 9872;
    float* se1 = sm + 9888;
    float* se2 = sm + 10188;
    unsigned char* sadj = (unsigned char*)(sm + 10488);
    float* sattb = sm + 15488;
    __shared__ int s_flags[2];

    const int tid  = threadIdx.x;
    const int lane = tid & 31;
    const int w    = tid >> 5;
    const int b    = blockIdx.x >> 3;
    const int hh   = blockIdx.x & 7;

    const float* hsrc = hin + (b * 8 + hh) * 4800;
    float* hdst = hout + (b * 8 + hh) * 4800;

    const int mode = detect_adj_mode<GAT_THREADS>(adjraw, s_flags);

    // ---- one-time loads ----
    for (int i = tid; i < 1200; i += GAT_THREADS)
        ((float4*)shh)[i] = ((const float4*)hsrc)[i];

    if (mode == 1) {
        const uint4* src = (const uint4*)((const unsigned char*)adjraw + b * 20000);
        for (int i = tid; i < 1250; i += GAT_THREADS)
            ((uint4*)sadj)[i] = src[i];
    } else if (mode == 0) {
        const int4* src = (const int4*)((const int*)adjraw + b * 20000);
        for (int i = tid; i < 5000; i += GAT_THREADS) {
            int4 v = src[i];
            ((uchar4*)sadj)[i] = make_uchar4(v.x != 0, v.y != 0, v.z != 0, v.w != 0);
        }
    } else {
        const float4* src = (const float4*)((const float*)adjraw + b * 20000);
        for (int i = tid; i < 5000; i += GAT_THREADS) {
            float4 v = src[i];
            ((uchar4*)sadj)[i] = make_uchar4(v.x != 0.f, v.y != 0.f, v.z != 0.f, v.w != 0.f);
        }
    }

    for (int l = 0; l < 3; l++) {
        const float* W = Wl + (l * 8 + hh) * 256;
        const float* a = al + (l * 8 + hh) * 32;
        if (tid < 256) {
            int j = tid >> 4, k = tid & 15;
            sWt[k * 16 + j] = W[tid];      // sWt[k][j] = W[j][k]  (r8 layout)
        }
        if (tid < 16) { sa1[tid] = a[tid]; sa2[tid] = a[16 + tid]; }
        __syncthreads();

        // ---- Wh = h @ W^T, e1 = Wh.a1, e2 = Wh.a2 (r8 exact) ----
        for (int base = tid; base < 4800; base += GAT_THREADS) {
            int n = base >> 4, jj = base & 15;
            const float* hr = shh + n * 16;
            float s = 0.f;
            #pragma unroll
            for (int k = 0; k < 16; k++) s = fmaf(hr[k], sWt[k * 16 + jj], s);
            sWh[base] = s;
            float p1 = s * sa1[jj];
            float p2 = s * sa2[jj];
            #pragma unroll
            for (int off = 8; off; off >>= 1) {
                p1 += __shfl_xor_sync(0xffffffffu, p1, off);
                p2 += __shfl_xor_sync(0xffffffffu, p2, off);
            }
            if (jj == 0) { se1[n] = p1; se2[n] = p2; }
        }
        __syncthreads();

        // ---- attention: 75 groups of 4 rows, r8 LPT schedule ----
        for (int k = 0; k < 4; k++) {
            int g;
            if (k == 0)      g = w;                                   // U0..U23
            else if (k == 1) g = (w == 3) ? 24
                               : (25 + w - (w > 3 ? 1 : 0));          // U24 / V25..47
            else if (k == 2) g = 48 + w;                              // V48..71
            else { if (w >= 3) break; g = 72 + w; }                   // V72..74

            const bool modeU = (g < 25);
            const int  r0    = modeU ? (g << 2) : ((g - 25) << 2);

            float* ab = sattb + w * 816;       // [204][4] per warp
            float rowc[4], selfe[4];
            float ssum[4] = {0.f, 0.f, 0.f, 0.f};

            if (modeU) {
                #pragma unroll
                for (int r = 0; r < 4; r++) {
                    rowc[r]  = se1[r0 + r];
                    float t  = rowc[r] + se2[r0 + r];
                    selfe[r] = (t > 0.f) ? t : 0.01f * t;
                }
                const float* cb = se2 + 100;
                const unsigned char* adjU = sadj + r0 * 200;
                #pragma unroll
                for (int kk = 0; kk < 6; kk++) {
                    int idx = lane + (kk << 5);
                    float cv = cb[idx];
                    float4 st;
                    float ev;
                    #define SCORE_U(r, comp) { \
                        float t = rowc[r] + cv; \
                        t = (t > 0.f) ? t : 0.01f * t; \
                        ev = __expf(t - selfe[r]); \
                        ev = adjU[r * 200 + idx] ? 0.f : ev; \
                        st.comp = ev; ssum[r] += ev; }
                    SCORE_U(0, x) SCORE_U(1, y) SCORE_U(2, z) SCORE_U(3, w)
                    *(float4*)&ab[idx * 4] = st;
                }
                if (lane < 8) {                    // tail: idx = 192+lane
                    int idx = 192 + lane;
                    float cv = cb[idx];
                    float4 st;
                    float ev;
                    SCORE_U(0, x) SCORE_U(1, y) SCORE_U(2, z) SCORE_U(3, w)
                    *(float4*)&ab[idx * 4] = st;
                    #undef SCORE_U
                }
            } else {
                #pragma unroll
                for (int r = 0; r < 4; r++) {
                    int node = 100 + r0 + r;
                    rowc[r]  = se2[node];
                    float t  = se1[node] + rowc[r];
                    selfe[r] = (t > 0.f) ? t : 0.01f * t;
                }
                const unsigned char* adjC = sadj + r0;
                #pragma unroll
                for (int kk = 0; kk < 3; kk++) {
                    int idx = lane + (kk << 5);
                    float cv = se1[idx];
                    unsigned int aw4 = *(const unsigned int*)(adjC + idx * 200);
                    float4 st;
                    float ev;
                    #define SCORE_V(r, comp) { \
                        float t = rowc[r] + cv; \
                        t = (t > 0.f) ? t : 0.01f * t; \
                        ev = __expf(t - selfe[r]); \
                        ev = ((aw4 >> (r * 8)) & 255u) ? 0.f : ev; \
                        st.comp = ev; ssum[r] += ev; }
                    SCORE_V(0, x) SCORE_V(1, y) SCORE_V(2, z) SCORE_V(3, w)
                    *(float4*)&ab[idx * 4] = st;
                }
                if (lane < 4) {                    // tail: idx = 96+lane
                    int idx = 96 + lane;
                    float cv = se1[idx];
                    unsigned int aw4 = *(const unsigned int*)(adjC + idx * 200);
                    float4 st;
                    float ev;
                    SCORE_V(0, x) SCORE_V(1, y) SCORE_V(2, z) SCORE_V(3, w)
                    *(float4*)&ab[idx * 4] = st;
                    #undef SCORE_V
                }
            }
            __syncwarp();

            // ssum tree (overlaps with aggregation latency below)
            #pragma unroll
            for (int off = 16; off; off >>= 1) {
                #pragma unroll
                for (int r = 0; r < 4; r++)
                    ssum[r] += __shfl_xor_sync(0xffffffffu, ssum[r], off);
            }
            float inv[4];
            #pragma unroll
            for (int r = 0; r < 4; r++)
                inv[r] = 1.f / (ssum[r] + 1.f);    // self term exp(0)=1

            // ---- aggregation over raw ev; r8 lane map, LDS.128 att loads ----
            const int q4 = (lane & 3) << 2, v4 = lane >> 2;
            float4 acc[4];
            #pragma unroll
            for (int r = 0; r < 4; r++) acc[r] = make_float4(0.f, 0.f, 0.f, 0.f);

            if (modeU) {
                const float* whb = sWh + 100 * 16 + q4;
                #pragma unroll 5
                for (int ii = 0; ii < 25; ii++) {
                    int i = v4 + (ii << 3);
                    float4 w4 = *(const float4*)&whb[i * 16];
                    float4 a4 = *(const float4*)&ab[i * 4];
                    acc[0].x = fmaf(a4.x, w4.x, acc[0].x);
                    acc[0].y = fmaf(a4.x, w4.y, acc[0].y);
                    acc[0].z = fmaf(a4.x, w4.z, acc[0].z);
                    acc[0].w = fmaf(a4.x, w4.w, acc[0].w);
                    acc[1].x = fmaf(a4.y, w4.x, acc[1].x);
                    acc[1].y = fmaf(a4.y, w4.y, acc[1].y);
                    acc[1].z = fmaf(a4.y, w4.z, acc[1].z);
                    acc[1].w = fmaf(a4.y, w4.w, acc[1].w);
                    acc[2].x = fmaf(a4.z, w4.x, acc[2].x);
                    acc[2].y = fmaf(a4.z, w4.y, acc[2].y);
                    acc[2].z = fmaf(a4.z, w4.z, acc[2].z);
                    acc[2].w = fmaf(a4.z, w4.w, acc[2].w);
                    acc[3].x = fmaf(a4.w, w4.x, acc[3].x);
                    acc[3].y = fmaf(a4.w, w4.y, acc[3].y);
                    acc[3].z = fmaf(a4.w, w4.z, acc[3].z);
                    acc[3].w = fmaf(a4.w, w4.w, acc[3].w);
                }
            } else {
                const float* whb = sWh + q4;
                #pragma unroll 4
                for (int ii = 0; ii < 13; ii++) {
                    int i = v4 + (ii << 3);
                    if (i < 100) {
                        float4 w4 = *(const float4*)&whb[i * 16];
                        float4 a4 = *(const float4*)&ab[i * 4];
                        acc[0].x = fmaf(a4.x, w4.x, acc[0].x);
                        acc[0].y = fmaf(a4.x, w4.y, acc[0].y);
                        acc[0].z = fmaf(a4.x, w4.z, acc[0].z);
                        acc[0].w = fmaf(a4.x, w4.w, acc[0].w);
                        acc[1].x = fmaf(a4.y, w4.x, acc[1].x);
                        acc[1].y = fmaf(a4.y, w4.y, acc[1].y);
                        acc[1].z = fmaf(a4.y, w4.z, acc[1].z);
                        acc[1].w = fmaf(a4.y, w4.w, acc[1].w);
                        acc[2].x = fmaf(a4.z, w4.x, acc[2].x);
                        acc[2].y = fmaf(a4.z, w4.y, acc[2].y);
                        acc[2].z = fmaf(a4.z, w4.z, acc[2].z);
                        acc[2].w = fmaf(a4.z, w4.w, acc[2].w);
                        acc[3].x = fmaf(a4.w, w4.x, acc[3].x);
                        acc[3].y = fmaf(a4.w, w4.y, acc[3].y);
                        acc[3].z = fmaf(a4.w, w4.z, acc[3].z);
                        acc[3].w = fmaf(a4.w, w4.w, acc[3].w);
                    }
                }
            }
            #pragma unroll
            for (int off = 4; off < 32; off <<= 1) {
                #pragma unroll
                for (int r = 0; r < 4; r++) {
                    acc[r].x += __shfl_xor_sync(0xffffffffu, acc[r].x, off);
                    acc[r].y += __shfl_xor_sync(0xffffffffu, acc[r].y, off);
                    acc[r].z += __shfl_xor_sync(0xffffffffu, acc[r].z, off);
                    acc[r].w += __shfl_xor_sync(0xffffffffu, acc[r].w, off);
                }
            }
            if (v4 == 0) {
                #pragma unroll
                for (int r = 0; r < 4; r++) {
                    int node = modeU ? (r0 + r) : (100 + r0 + r);
                    float4 ws = *(const float4*)&sWh[node * 16 + q4];
                    float4 res;
                    res.x = (acc[r].x + ws.x) * inv[r];
                    res.y = (acc[r].y + ws.y) * inv[r];
                    res.z = (acc[r].z + ws.z) * inv[r];
                    res.w = (acc[r].w + ws.w) * inv[r];
                    res.x = (res.x > 0.f) ? res.x : expm1f(res.x);
                    res.y = (res.y > 0.f) ? res.y : expm1f(res.y);
                    res.z = (res.z > 0.f) ? res.z : expm1f(res.z);
                    res.w = (res.w > 0.f) ? res.w : expm1f(res.w);
                    if (l == 2)
                        *(float4*)&hdst[node * 16 + q4] = res;
                    else
                        *(float4*)&shh[node * 16 + q4] = res;
                }
            }
            __syncwarp();
        }
        __syncthreads();   // shh fully written before next layer's Wh phase
    }
}

// ---------------------------------------------------------------------------
// pu = hE[:, :U] @ W1^T ; pv = hE[:, U:] @ W2^T   (r8 exact)
// ---------------------------------------------------------------------------
__global__ void __launch_bounds__(256, 1) pupv_kernel(
    const float* __restrict__ hE,
    const float* __restrict__ Wlast,  // [128][257]
    float* __restrict__ pu, float* __restrict__ pv)
{
    extern __shared__ float sm[];
    float* hsm = sm;           // 20*132
    float* Wsm = sm + 2640;    // 128*132

    const int blk = blockIdx.x;
    const int b = blk / 15, t = blk % 15;
    const bool isU = (t < 5);
    const int n0 = isU ? t * 20 : 100 + (t - 5) * 20;
    const int coff = isU ? 0 : 128;
    const int tid = threadIdx.x;

    for (int i = tid; i < 128 * 128; i += 256) {
        int e = i >> 7, k = i & 127;
        Wsm[e * 132 + k] = Wlast[e * 257 + coff + k];
    }
    for (int i = tid; i < 20 * 128; i += 256) {
        int n = i >> 7, k = i & 127;
        hsm[n * 132 + k] = hE[b * 38400 + (n0 + n) * 128 + k];
    }
    __syncthreads();

    const int e = tid & 127, half = tid >> 7;
    float acc[10];
    #pragma unroll
    for (int n = 0; n < 10; n++) acc[n] = 0.f;
    const float* wrow  = Wsm + e * 132;
    const float* hbase = hsm + (half * 10) * 132;

    #pragma unroll 8
    for (int k4 = 0; k4 < 32; k4++) {
        float4 wv = *(const float4*)&wrow[k4 * 4];
        #pragma unroll
        for (int n = 0; n < 10; n++) {
            float4 hv = *(const float4*)&hbase[n * 132 + k4 * 4];
            acc[n] = fmaf(wv.x, hv.x, acc[n]);
            acc[n] = fmaf(wv.y, hv.y, acc[n]);
            acc[n] = fmaf(wv.z, hv.z, acc[n]);
            acc[n] = fmaf(wv.w, hv.w, acc[n]);
        }
    }
    int nodeBase = isU ? (b * 100 + n0 + half * 10) : (b * 200 + (n0 - 100) + half * 10);
    float* dst = isU ? (pu + (size_t)nodeBase * 128) : (pv + (size_t)nodeBase * 128);
    #pragma unroll
    for (int n = 0; n < 10; n++) dst[n * 128 + e] = acc[n];
}

// ---------------------------------------------------------------------------
// out[b,u,v,:] = mask*(pu[b,u,:] + pv[b,v,:]) + weights[b,u,v]*wl  (r8 exact)
// ---------------------------------------------------------------------------
__global__ void __launch_bounds__(512, 1) out_kernel(
    const float* __restrict__ pu, const float* __restrict__ pv,
    const void* __restrict__ adjraw, const float* __restrict__ weights,
    const float* __restrict__ Wlast, float* __restrict__ out)
{
    extern __shared__ float sm[];
    float* spv = sm;            // 200*128
    float* spu = sm + 25600;    // up to 12*128
    float* swl = sm + 27136;    // 128
    __shared__ int s_flags[2];

    const int b = blockIdx.x / 9, gslice = blockIdx.x % 9;
    const int u0 = (gslice * 100) / 9;
    const int u1 = ((gslice + 1) * 100) / 9;
    const int nu = u1 - u0;
    const int tid = threadIdx.x, lane = tid & 31, w = tid >> 5;

    const int mode = detect_adj_mode<512>(adjraw, s_flags);

    for (int i = tid; i < 6400; i += 512)
        ((float4*)spv)[i] = ((const float4*)(pv + b * 25600))[i];
    for (int i = tid; i < nu * 32; i += 512)
        ((float4*)spu)[i] = ((const float4*)(pu + (b * 100 + u0) * 128))[i];
    if (tid < 128) swl[tid] = Wlast[tid * 257 + 256];
    __syncthreads();

    const float4 wl4 = *(const float4*)&swl[lane * 4];
    for (int iu = 0; iu < nu; iu++) {
        const int u = u0 + iu;
        const int abase = (b * 100 + u) * 200;
        const float* wrow = weights + abase;
        const float4 pu4 = *(const float4*)&spu[iu * 128 + lane * 4];
        float* obase = out + ((size_t)(b * 100 + u)) * 200 * 128;
        for (int v = w; v < 200; v += 16) {
            float msk;
            if (mode == 0)      msk = ((const int*)adjraw)[abase + v] ? 0.f : 1.f;
            else if (mode == 1) msk = ((const unsigned char*)adjraw)[abase + v] ? 0.f : 1.f;
            else                msk = (((const float*)adjraw)[abase + v] != 0.f) ? 0.f : 1.f;
            const float wt  = wrow[v];
            const float4 pv4 = *(const float4*)&spv[v * 128 + lane * 4];
            float4 o;
            o.x = msk * (pu4.x + pv4.x) + wt * wl4.x;
            o.y = msk * (pu4.y + pv4.y) + wt * wl4.y;
            o.z = msk * (pu4.z + pv4.z) + wt * wl4.z;
            o.w = msk * (pu4.w + pv4.w) + wt * wl4.w;
            __stcs((float4*)&obase[(size_t)v * 128 + lane * 4], o);
        }
    }
}

// ---------------------------------------------------------------------------
extern "C" void kernel_launch(void* const* d_in, const int* in_sizes, int n_in,
                              void* d_out, int out_size)
{
    (void)in_sizes; (void)n_in; (void)out_size;
    const float* x              = (const float*)d_in[0];
    const void*  adj_raw        = (const void*)d_in[1];
    const float* weights        = (const float*)d_in[2];
    const float* Wlayers        = (const float*)d_in[3];
    const float* alayers        = (const float*)d_in[4];
    const float* Wlast          = (const float*)d_in[5];
    float* out = (float*)d_out;

    float *dH, *dpu, *dpv;
    cudaGetSymbolAddress((void**)&dH, g_hE);
    cudaGetSymbolAddress((void**)&dpu, g_pu);
    cudaGetSymbolAddress((void**)&dpv, g_pv);

    const int SM1 = 35072 * 4;                  // 140288
    const int SM2 = (2640 + 128 * 132) * 4;     // 78144
    const int SM3 = (27136 + 128) * 4;          // 109056
    cudaFuncSetAttribute(gat_fused_kernel, cudaFuncAttributeMaxDynamicSharedMemorySize, SM1);
    cudaFuncSetAttribute(pupv_kernel,      cudaFuncAttributeMaxDynamicSharedMemorySize, SM2);
    cudaFuncSetAttribute(out_kernel,       cudaFuncAttributeMaxDynamicSharedMemorySize, SM3);

    gat_fused_kernel<<<128, GAT_THREADS, SM1>>>(x, adj_raw, Wlayers, alayers, dH);
    pupv_kernel<<<240, 256, SM2>>>(dH, Wlast, dpu, dpv);
    out_kernel<<<144, 512, SM3>>>(dpu, dpv, adj_raw, weights, Wlast, out);
}

// round 14
// speedup vs baseline: 1.4548x; 1.0237x over previous
#include <cuda_runtime.h>
#include <cuda_bf16.h>
#include <math.h>

// B=16, N=300, U=100, V=200, E=128, H=8, hd=16, L=3
// out: [16, 20000, 128] f32 (163.8 MB)

// Scratch (allocation-free: device globals)
__device__ float g_hE[16 * 38400];
__device__ float g_pu[16 * 100 * 128];
__device__ float g_pv[16 * 200 * 128];

// ---------------------------------------------------------------------------
// adj dtype detection, inlined per consumer CTA. 2048-word window:
//   any word == 0x3F800000           -> float32
//   any word not in {0,1,0x3F800000} -> packed uint8 (p=0.3 -> certain)
//   else                             -> int32
// ---------------------------------------------------------------------------
template <int NT>
__device__ __forceinline__ int detect_adj_mode(const void* adjraw, int* s_flags)
{
    const unsigned int* aw = (const unsigned int*)adjraw;
    int tid = threadIdx.x;
    if (tid == 0) { s_flags[0] = 0; s_flags[1] = 0; }
    __syncthreads();
    int f32 = 0, multi = 0;
    #pragma unroll
    for (int i = tid; i < 2048; i += NT) {
        unsigned int v = aw[i];
        f32   |= (v == 0x3F800000u);
        multi |= (v != 0u && v != 1u && v != 0x3F800000u);
    }
    if (__any_sync(0xffffffffu, f32)   && (tid & 31) == 0) atomicOr(&s_flags[0], 1);
    if (__any_sync(0xffffffffu, multi) && (tid & 31) == 0) atomicOr(&s_flags[1], 1);
    __syncthreads();
    return s_flags[0] ? 2 : (s_flags[1] ? 1 : 0);   // 2=f32, 1=u8, 0=i32
}

// ---------------------------------------------------------------------------
// Fused 3-layer GAT: one CTA per (b, head). 768 threads (24 warps).
// (r13 tied-best version: r8 structure + transposed att staging ab[idx][4])
// smem floats:
//   [0,4800)      sWh   [300][16]
//   [4800,9600)   shh   persistent h [300][16]
//   [9600,9856)   sWt   16x16 transposed
//   [9856,9872)   sa1   [9872,9888) sa2
//   [9888,10188)  se1[300]   [10188,10488) se2[300]
//   [10488,15488) sadj (20000 B, canonical u8)
//   [15488,35072) sattb [24 warps][204][4]
// total 140288 bytes -> 1 CTA/SM, 24 warps
// ---------------------------------------------------------------------------
#define GAT_THREADS 768

__global__ void __launch_bounds__(GAT_THREADS, 1) gat_fused_kernel(
    const float* __restrict__ hin,
    const void*  __restrict__ adjraw,
    const float* __restrict__ Wl,   // [3][8][16][16]
    const float* __restrict__ al,   // [3][8][32]
    float* __restrict__ hout)
{
    extern __shared__ float sm[];
    float* sWh = sm;
    float* shh = sm + 4800;
    float* sWt = sm + 9600;
    float* sa1 = sm + 9856;
    float* sa2 = sm + 9872;
    float* se1 = sm + 9888;
    float* se2 = sm + 10188;
    unsigned char* sadj = (unsigned char*)(sm + 10488);
    float* sattb = sm + 15488;
    __shared__ int s_flags[2];

    const int tid  = threadIdx.x;
    const int lane = tid & 31;
    const int w    = tid >> 5;
    const int b    = blockIdx.x >> 3;
    const int hh   = blockIdx.x & 7;

    const float* hsrc = hin + (b * 8 + hh) * 4800;
    float* hdst = hout + (b * 8 + hh) * 4800;

    const int mode = detect_adj_mode<GAT_THREADS>(adjraw, s_flags);

    // ---- one-time loads ----
    for (int i = tid; i < 1200; i += GAT_THREADS)
        ((float4*)shh)[i] = ((const float4*)hsrc)[i];

    if (mode == 1) {
        const uint4* src = (const uint4*)((const unsigned char*)adjraw + b * 20000);
        for (int i = tid; i < 1250; i += GAT_THREADS)
            ((uint4*)sadj)[i] = src[i];
    } else if (mode == 0) {
        const int4* src = (const int4*)((const int*)adjraw + b * 20000);
        for (int i = tid; i < 5000; i += GAT_THREADS) {
            int4 v = src[i];
            ((uchar4*)sadj)[i] = make_uchar4(v.x != 0, v.y != 0, v.z != 0, v.w != 0);
        }
    } else {
        const float4* src = (const float4*)((const float*)adjraw + b * 20000);
        for (int i = tid; i < 5000; i += GAT_THREADS) {
            float4 v = src[i];
            ((uchar4*)sadj)[i] = make_uchar4(v.x != 0.f, v.y != 0.f, v.z != 0.f, v.w != 0.f);
        }
    }

    for (int l = 0; l < 3; l++) {
        const float* W = Wl + (l * 8 + hh) * 256;
        const float* a = al + (l * 8 + hh) * 32;
        if (tid < 256) {
            int j = tid >> 4, k = tid & 15;
            sWt[k * 16 + j] = W[tid];      // sWt[k][j] = W[j][k]
        }
        if (tid < 16) { sa1[tid] = a[tid]; sa2[tid] = a[16 + tid]; }
        __syncthreads();

        // ---- Wh = h @ W^T, e1 = Wh.a1, e2 = Wh.a2 ----
        for (int base = tid; base < 4800; base += GAT_THREADS) {
            int n = base >> 4, jj = base & 15;
            const float* hr = shh + n * 16;
            float s = 0.f;
            #pragma unroll
            for (int k = 0; k < 16; k++) s = fmaf(hr[k], sWt[k * 16 + jj], s);
            sWh[base] = s;
            float p1 = s * sa1[jj];
            float p2 = s * sa2[jj];
            #pragma unroll
            for (int off = 8; off; off >>= 1) {
                p1 += __shfl_xor_sync(0xffffffffu, p1, off);
                p2 += __shfl_xor_sync(0xffffffffu, p2, off);
            }
            if (jj == 0) { se1[n] = p1; se2[n] = p2; }
        }
        __syncthreads();

        // ---- attention: 75 groups of 4 rows, LPT schedule ----
        for (int k = 0; k < 4; k++) {
            int g;
            if (k == 0)      g = w;                                   // U0..U23
            else if (k == 1) g = (w == 3) ? 24
                               : (25 + w - (w > 3 ? 1 : 0));          // U24 / V25..47
            else if (k == 2) g = 48 + w;                              // V48..71
            else { if (w >= 3) break; g = 72 + w; }                   // V72..74

            const bool modeU = (g < 25);
            const int  r0    = modeU ? (g << 2) : ((g - 25) << 2);

            float* ab = sattb + w * 816;       // [204][4] per warp
            float rowc[4], selfe[4];
            float ssum[4] = {0.f, 0.f, 0.f, 0.f};

            if (modeU) {
                #pragma unroll
                for (int r = 0; r < 4; r++) {
                    rowc[r]  = se1[r0 + r];
                    float t  = rowc[r] + se2[r0 + r];
                    selfe[r] = (t > 0.f) ? t : 0.01f * t;
                }
                const float* cb = se2 + 100;
                const unsigned char* adjU = sadj + r0 * 200;
                #pragma unroll
                for (int kk = 0; kk < 6; kk++) {
                    int idx = lane + (kk << 5);
                    float cv = cb[idx];
                    float4 st;
                    float ev;
                    #define SCORE_U(r, comp) { \
                        float t = rowc[r] + cv; \
                        t = (t > 0.f) ? t : 0.01f * t; \
                        ev = __expf(t - selfe[r]); \
                        ev = adjU[r * 200 + idx] ? 0.f : ev; \
                        st.comp = ev; ssum[r] += ev; }
                    SCORE_U(0, x) SCORE_U(1, y) SCORE_U(2, z) SCORE_U(3, w)
                    *(float4*)&ab[idx * 4] = st;
                }
                if (lane < 8) {                    // tail: idx = 192+lane
                    int idx = 192 + lane;
                    float cv = cb[idx];
                    float4 st;
                    float ev;
                    SCORE_U(0, x) SCORE_U(1, y) SCORE_U(2, z) SCORE_U(3, w)
                    *(float4*)&ab[idx * 4] = st;
                    #undef SCORE_U
                }
            } else {
                #pragma unroll
                for (int r = 0; r < 4; r++) {
                    int node = 100 + r0 + r;
                    rowc[r]  = se2[node];
                    float t  = se1[node] + rowc[r];
                    selfe[r] = (t > 0.f) ? t : 0.01f * t;
                }
                const unsigned char* adjC = sadj + r0;
                #pragma unroll
                for (int kk = 0; kk < 3; kk++) {
                    int idx = lane + (kk << 5);
                    float cv = se1[idx];
                    unsigned int aw4 = *(const unsigned int*)(adjC + idx * 200);
                    float4 st;
                    float ev;
                    #define SCORE_V(r, comp) { \
                        float t = rowc[r] + cv; \
                        t = (t > 0.f) ? t : 0.01f * t; \
                        ev = __expf(t - selfe[r]); \
                        ev = ((aw4 >> (r * 8)) & 255u) ? 0.f : ev; \
                        st.comp = ev; ssum[r] += ev; }
                    SCORE_V(0, x) SCORE_V(1, y) SCORE_V(2, z) SCORE_V(3, w)
                    *(float4*)&ab[idx * 4] = st;
                }
                if (lane < 4) {                    // tail: idx = 96+lane
                    int idx = 96 + lane;
                    float cv = se1[idx];
                    unsigned int aw4 = *(const unsigned int*)(adjC + idx * 200);
                    float4 st;
                    float ev;
                    SCORE_V(0, x) SCORE_V(1, y) SCORE_V(2, z) SCORE_V(3, w)
                    *(float4*)&ab[idx * 4] = st;
                    #undef SCORE_V
                }
            }
            __syncwarp();

            // ssum tree (overlaps with aggregation latency below)
            #pragma unroll
            for (int off = 16; off; off >>= 1) {
                #pragma unroll
                for (int r = 0; r < 4; r++)
                    ssum[r] += __shfl_xor_sync(0xffffffffu, ssum[r], off);
            }
            float inv[4];
            #pragma unroll
            for (int r = 0; r < 4; r++)
                inv[r] = 1.f / (ssum[r] + 1.f);    // self term exp(0)=1

            // ---- aggregation over raw ev; normalize at the end ----
            const int q4 = (lane & 3) << 2, v4 = lane >> 2;
            float4 acc[4];
            #pragma unroll
            for (int r = 0; r < 4; r++) acc[r] = make_float4(0.f, 0.f, 0.f, 0.f);

            if (modeU) {
                const float* whb = sWh + 100 * 16 + q4;
                #pragma unroll 5
                for (int ii = 0; ii < 25; ii++) {
                    int i = v4 + (ii << 3);
                    float4 w4 = *(const float4*)&whb[i * 16];
                    float4 a4 = *(const float4*)&ab[i * 4];
                    acc[0].x = fmaf(a4.x, w4.x, acc[0].x);
                    acc[0].y = fmaf(a4.x, w4.y, acc[0].y);
                    acc[0].z = fmaf(a4.x, w4.z, acc[0].z);
                    acc[0].w = fmaf(a4.x, w4.w, acc[0].w);
                    acc[1].x = fmaf(a4.y, w4.x, acc[1].x);
                    acc[1].y = fmaf(a4.y, w4.y, acc[1].y);
                    acc[1].z = fmaf(a4.y, w4.z, acc[1].z);
                    acc[1].w = fmaf(a4.y, w4.w, acc[1].w);
                    acc[2].x = fmaf(a4.z, w4.x, acc[2].x);
                    acc[2].y = fmaf(a4.z, w4.y, acc[2].y);
                    acc[2].z = fmaf(a4.z, w4.z, acc[2].z);
                    acc[2].w = fmaf(a4.z, w4.w, acc[2].w);
                    acc[3].x = fmaf(a4.w, w4.x, acc[3].x);
                    acc[3].y = fmaf(a4.w, w4.y, acc[3].y);
                    acc[3].z = fmaf(a4.w, w4.z, acc[3].z);
                    acc[3].w = fmaf(a4.w, w4.w, acc[3].w);
                }
            } else {
                const float* whb = sWh + q4;
                #pragma unroll 4
                for (int ii = 0; ii < 13; ii++) {
                    int i = v4 + (ii << 3);
                    if (i < 100) {
                        float4 w4 = *(const float4*)&whb[i * 16];
                        float4 a4 = *(const float4*)&ab[i * 4];
                        acc[0].x = fmaf(a4.x, w4.x, acc[0].x);
                        acc[0].y = fmaf(a4.x, w4.y, acc[0].y);
                        acc[0].z = fmaf(a4.x, w4.z, acc[0].z);
                        acc[0].w = fmaf(a4.x, w4.w, acc[0].w);
                        acc[1].x = fmaf(a4.y, w4.x, acc[1].x);
                        acc[1].y = fmaf(a4.y, w4.y, acc[1].y);
                        acc[1].z = fmaf(a4.y, w4.z, acc[1].z);
                        acc[1].w = fmaf(a4.y, w4.w, acc[1].w);
                        acc[2].x = fmaf(a4.z, w4.x, acc[2].x);
                        acc[2].y = fmaf(a4.z, w4.y, acc[2].y);
                        acc[2].z = fmaf(a4.z, w4.z, acc[2].z);
                        acc[2].w = fmaf(a4.z, w4.w, acc[2].w);
                        acc[3].x = fmaf(a4.w, w4.x, acc[3].x);
                        acc[3].y = fmaf(a4.w, w4.y, acc[3].y);
                        acc[3].z = fmaf(a4.w, w4.z, acc[3].z);
                        acc[3].w = fmaf(a4.w, w4.w, acc[3].w);
                    }
                }
            }
            #pragma unroll
            for (int off = 4; off < 32; off <<= 1) {
                #pragma unroll
                for (int r = 0; r < 4; r++) {
                    acc[r].x += __shfl_xor_sync(0xffffffffu, acc[r].x, off);
                    acc[r].y += __shfl_xor_sync(0xffffffffu, acc[r].y, off);
                    acc[r].z += __shfl_xor_sync(0xffffffffu, acc[r].z, off);
                    acc[r].w += __shfl_xor_sync(0xffffffffu, acc[r].w, off);
                }
            }
            if (v4 == 0) {
                #pragma unroll
                for (int r = 0; r < 4; r++) {
                    int node = modeU ? (r0 + r) : (100 + r0 + r);
                    float4 ws = *(const float4*)&sWh[node * 16 + q4];
                    float4 res;
                    res.x = (acc[r].x + ws.x) * inv[r];
                    res.y = (acc[r].y + ws.y) * inv[r];
                    res.z = (acc[r].z + ws.z) * inv[r];
                    res.w = (acc[r].w + ws.w) * inv[r];
                    res.x = (res.x > 0.f) ? res.x : expm1f(res.x);
                    res.y = (res.y > 0.f) ? res.y : expm1f(res.y);
                    res.z = (res.z > 0.f) ? res.z : expm1f(res.z);
                    res.w = (res.w > 0.f) ? res.w : expm1f(res.w);
                    if (l == 2)
                        *(float4*)&hdst[node * 16 + q4] = res;
                    else
                        *(float4*)&shh[node * 16 + q4] = res;
                }
            }
            __syncwarp();
        }
        __syncthreads();   // shh fully written before next layer's Wh phase
    }
}

// ---------------------------------------------------------------------------
// pu = hE[:, :U] @ W1^T ; pv = hE[:, U:] @ W2^T   (r8 exact)
// ---------------------------------------------------------------------------
__global__ void __launch_bounds__(256, 1) pupv_kernel(
    const float* __restrict__ hE,
    const float* __restrict__ Wlast,  // [128][257]
    float* __restrict__ pu, float* __restrict__ pv)
{
    extern __shared__ float sm[];
    float* hsm = sm;           // 20*132
    float* Wsm = sm + 2640;    // 128*132

    const int blk = blockIdx.x;
    const int b = blk / 15, t = blk % 15;
    const bool isU = (t < 5);
    const int n0 = isU ? t * 20 : 100 + (t - 5) * 20;
    const int coff = isU ? 0 : 128;
    const int tid = threadIdx.x;

    for (int i = tid; i < 128 * 128; i += 256) {
        int e = i >> 7, k = i & 127;
        Wsm[e * 132 + k] = Wlast[e * 257 + coff + k];
    }
    for (int i = tid; i < 20 * 128; i += 256) {
        int n = i >> 7, k = i & 127;
        hsm[n * 132 + k] = hE[b * 38400 + (n0 + n) * 128 + k];
    }
    __syncthreads();

    const int e = tid & 127, half = tid >> 7;
    float acc[10];
    #pragma unroll
    for (int n = 0; n < 10; n++) acc[n] = 0.f;
    const float* wrow  = Wsm + e * 132;
    const float* hbase = hsm + (half * 10) * 132;

    #pragma unroll 8
    for (int k4 = 0; k4 < 32; k4++) {
        float4 wv = *(const float4*)&wrow[k4 * 4];
        #pragma unroll
        for (int n = 0; n < 10; n++) {
            float4 hv = *(const float4*)&hbase[n * 132 + k4 * 4];
            acc[n] = fmaf(wv.x, hv.x, acc[n]);
            acc[n] = fmaf(wv.y, hv.y, acc[n]);
            acc[n] = fmaf(wv.z, hv.z, acc[n]);
            acc[n] = fmaf(wv.w, hv.w, acc[n]);
        }
    }
    int nodeBase = isU ? (b * 100 + n0 + half * 10) : (b * 200 + (n0 - 100) + half * 10);
    float* dst = isU ? (pu + (size_t)nodeBase * 128) : (pv + (size_t)nodeBase * 128);
    #pragma unroll
    for (int n = 0; n < 10; n++) dst[n * 128 + e] = acc[n];
}

// ---------------------------------------------------------------------------
// out[b,u,v,:] = mask*(pu[b,u,:] + pv[b,v,:]) + weights[b,u,v]*wl
// NEW: tiled in u AND v. grid 16b x 4u x 4v = 256 CTAs, 256 thr,
//      smem 39KB -> multiple CTAs/SM (overlapped prologue + stores).
// ---------------------------------------------------------------------------
__global__ void __launch_bounds__(256, 2) out_kernel(
    const float* __restrict__ pu, const float* __restrict__ pv,
    const void* __restrict__ adjraw, const float* __restrict__ weights,
    const float* __restrict__ Wlast, float* __restrict__ out)
{
    extern __shared__ float sm[];
    float* spu = sm;            // 25*128 = 3200
    float* spv = sm + 3200;     // 50*128 = 6400
    float* swl = sm + 9600;     // 128
    __shared__ int s_flags[2];

    const int blk = blockIdx.x;
    const int b  = blk >> 4;
    const int us = (blk >> 2) & 3;
    const int vs = blk & 3;
    const int u0 = us * 25;
    const int v0 = vs * 50;
    const int tid = threadIdx.x, lane = tid & 31, w = tid >> 5;

    const int mode = detect_adj_mode<256>(adjraw, s_flags);

    for (int i = tid; i < 800; i += 256)    // pu tile: 25*32 float4
        ((float4*)spu)[i] = ((const float4*)(pu + (b * 100 + u0) * 128))[i];
    for (int i = tid; i < 1600; i += 256)   // pv tile: 50*32 float4
        ((float4*)spv)[i] = ((const float4*)(pv + (b * 200 + v0) * 128))[i];
    if (tid < 128) swl[tid] = Wlast[tid * 257 + 256];
    __syncthreads();

    const float4 wl4 = *(const float4*)&swl[lane * 4];
    for (int iu = 0; iu < 25; iu++) {
        const int u = u0 + iu;
        const int abase = (b * 100 + u) * 200;
        const float* wrow = weights + abase;
        const float4 pu4 = *(const float4*)&spu[iu * 128 + lane * 4];
        float* obase = out + (((size_t)(b * 100 + u)) * 200 + v0) * 128;
        for (int iv = w; iv < 50; iv += 8) {
            const int v = v0 + iv;
            float msk;
            if (mode == 0)      msk = ((const int*)adjraw)[abase + v] ? 0.f : 1.f;
            else if (mode == 1) msk = ((const unsigned char*)adjraw)[abase + v] ? 0.f : 1.f;
            else                msk = (((const float*)adjraw)[abase + v] != 0.f) ? 0.f : 1.f;
            const float wt  = wrow[v];
            const float4 pv4 = *(const float4*)&spv[iv * 128 + lane * 4];
            float4 o;
            o.x = msk * (pu4.x + pv4.x) + wt * wl4.x;
            o.y = msk * (pu4.y + pv4.y) + wt * wl4.y;
            o.z = msk * (pu4.z + pv4.z) + wt * wl4.z;
            o.w = msk * (pu4.w + pv4.w) + wt * wl4.w;
            __stcs((float4*)&obase[(size_t)iv * 128 + lane * 4], o);
        }
    }
}

// ---------------------------------------------------------------------------
extern "C" void kernel_launch(void* const* d_in, const int* in_sizes, int n_in,
                              void* d_out, int out_size)
{
    (void)in_sizes; (void)n_in; (void)out_size;
    const float* x              = (const float*)d_in[0];
    const void*  adj_raw        = (const void*)d_in[1];
    const float* weights        = (const float*)d_in[2];
    const float* Wlayers        = (const float*)d_in[3];
    const float* alayers        = (const float*)d_in[4];
    const float* Wlast          = (const float*)d_in[5];
    float* out = (float*)d_out;

    float *dH, *dpu, *dpv;
    cudaGetSymbolAddress((void**)&dH, g_hE);
    cudaGetSymbolAddress((void**)&dpu, g_pu);
    cudaGetSymbolAddress((void**)&dpv, g_pv);

    const int SM1 = 35072 * 4;                  // 140288
    const int SM2 = (2640 + 128 * 132) * 4;     // 78144
    const int SM3 = (9600 + 128) * 4 + 256;     // ~39KB
    cudaFuncSetAttribute(gat_fused_kernel, cudaFuncAttributeMaxDynamicSharedMemorySize, SM1);
    cudaFuncSetAttribute(pupv_kernel,      cudaFuncAttributeMaxDynamicSharedMemorySize, SM2);
    cudaFuncSetAttribute(out_kernel,       cudaFuncAttributeMaxDynamicSharedMemorySize, SM3);

    gat_fused_kernel<<<128, GAT_THREADS, SM1>>>(x, adj_raw, Wlayers, alayers, dH);
    pupv_kernel<<<240, 256, SM2>>>(dH, Wlast, dpu, dpv);
    out_kernel<<<256, 256, SM3>>>(dpu, dpv, adj_raw, weights, Wlast, out);
}